// round 2
// baseline (speedup 1.0000x reference)
#include <cuda_runtime.h>

// Problem constants
#define BATCH 4
#define HH    128
#define WW    128
#define CC    256
#define GG    16
#define KK2   9
#define CR    64
#define EE    144            // K2*G
#define NPIX  (BATCH*HH*WW)  // 65536

// ---------------------------------------------------------------------------
// Fold BN into w1/b1:  h = (x@w1 + b1 - mean)*s + beta,  s = gamma/sqrt(var+eps)
//   w1f[c][d] = w1[c][d]*s[d];  b1f[d] = (b1[d]-mean[d])*s[d] + beta[d]
// ---------------------------------------------------------------------------
__device__ float g_w1f[CC * CR];
__device__ float g_b1f[CR];

__global__ void fold_kernel(const float* __restrict__ w1, const float* __restrict__ b1,
                            const float* __restrict__ gamma, const float* __restrict__ beta,
                            const float* __restrict__ mean, const float* __restrict__ var) {
    int idx = blockIdx.x * blockDim.x + threadIdx.x;
    if (idx < CC * CR) {
        int d = idx & (CR - 1);
        float s = gamma[d] * rsqrtf(var[d] + 1e-3f);
        g_w1f[idx] = w1[idx] * s;
        if (idx < CR) {
            g_b1f[idx] = (b1[idx] - mean[idx]) * s + beta[idx];
        }
    }
}

// ---------------------------------------------------------------------------
// Kernel generation, static smem only (<= 48KB):
//   h   = relu(x[p]@w1f + b1f)   (256 -> 64), K tiled in 4 chunks of 64
//   ker = h@w2 + b2              (64 -> 144), 2 column passes (j=0..4, j=5..8)
// Block = 256 threads, 64 pixels. Thread (tx,ty) = (tid&15, tid>>4):
//   phase1: 4 pixels x 4 channels per thread; phase2: 4 pixels x <=5 cols.
// smem:
//   sA: [64][68]  x-chunk (phase1) then h (phase2)        17408 B
//   sB: [64][80]  w1-chunk (64x64 used) then w2 half      20480 B
// ---------------------------------------------------------------------------
#define SA_STRIDE 68
#define SB_STRIDE 80

__global__ void __launch_bounds__(256)
kgen_kernel(const float* __restrict__ x, const float* __restrict__ w2,
            const float* __restrict__ b2, float* __restrict__ kout) {
    __shared__ float sA[64 * SA_STRIDE];
    __shared__ float sB[64 * SB_STRIDE];

    const int tid = threadIdx.x;
    const int p0  = blockIdx.x * 64;
    const int tx = tid & 15;
    const int ty = tid >> 4;

    const float4* x4   = (const float4*)x;         // [NPIX][64] float4
    const float4* w1f4 = (const float4*)g_w1f;     // [256][16]  float4
    const float4* w24  = (const float4*)w2;        // [64][36]   float4

    // ---------------- phase 1: h = x @ w1f, K tiled ----------------
    float acc[4][4];
    #pragma unroll
    for (int i = 0; i < 4; i++)
        #pragma unroll
        for (int j = 0; j < 4; j++) acc[i][j] = 0.f;

    for (int kc = 0; kc < 4; kc++) {
        // load x chunk: 64 px x 64 ch = 1024 float4
        #pragma unroll
        for (int i = 0; i < 4; i++) {
            int idx = tid + 256 * i;
            int p   = idx >> 4;
            int c4  = idx & 15;
            *(float4*)(sA + p * SA_STRIDE + c4 * 4) =
                x4[(size_t)(p0 + p) * 64 + kc * 16 + c4];
        }
        // load w1f chunk: rows kc*64..+63, 64 cols = 1024 float4
        #pragma unroll
        for (int i = 0; i < 4; i++) {
            int idx = tid + 256 * i;
            int r   = idx >> 4;
            int c4  = idx & 15;
            *(float4*)(sB + r * 64 + c4 * 4) = w1f4[(kc * 64 + r) * 16 + c4];
        }
        __syncthreads();

        #pragma unroll 4
        for (int k = 0; k < 64; k++) {
            float4 bv = *(const float4*)(sB + k * 64 + tx * 4);
            float a0 = sA[(ty * 4 + 0) * SA_STRIDE + k];
            float a1 = sA[(ty * 4 + 1) * SA_STRIDE + k];
            float a2 = sA[(ty * 4 + 2) * SA_STRIDE + k];
            float a3 = sA[(ty * 4 + 3) * SA_STRIDE + k];
            acc[0][0] += a0 * bv.x; acc[0][1] += a0 * bv.y; acc[0][2] += a0 * bv.z; acc[0][3] += a0 * bv.w;
            acc[1][0] += a1 * bv.x; acc[1][1] += a1 * bv.y; acc[1][2] += a1 * bv.z; acc[1][3] += a1 * bv.w;
            acc[2][0] += a2 * bv.x; acc[2][1] += a2 * bv.y; acc[2][2] += a2 * bv.z; acc[2][3] += a2 * bv.w;
            acc[3][0] += a3 * bv.x; acc[3][1] += a3 * bv.y; acc[3][2] += a3 * bv.z; acc[3][3] += a3 * bv.w;
        }
        __syncthreads();
    }

    // bias + relu -> h into sA
    #pragma unroll
    for (int j = 0; j < 4; j++) {
        float bj = g_b1f[tx * 4 + j];
        #pragma unroll
        for (int i = 0; i < 4; i++) {
            float v = acc[i][j] + bj;
            sA[(ty * 4 + i) * SA_STRIDE + tx * 4 + j] = fmaxf(v, 0.f);
        }
    }
    __syncthreads();

    // ---------------- phase 2: ker = h @ w2 + b2, 2 column passes ----------------
    #pragma unroll
    for (int pass = 0; pass < 2; pass++) {
        const int jlo = pass ? 5 : 0;
        const int jn  = pass ? 4 : 5;      // columns jlo*16 .. jlo*16 + 16*jn
        const int c40 = jlo * 4;           // float4 column offset within a w2 row

        // stage w2[:, jlo*16 : jlo*16+16*jn] -> sB[64][16*jn] (stride SB_STRIDE)
        const int nf4 = 64 * 4 * jn;       // float4 count: 1280 or 1024
        const int c4n = 4 * jn;            // float4 per row: 20 or 16
        for (int idx = tid; idx < nf4; idx += 256) {
            int r  = idx / c4n;
            int c4 = idx - r * c4n;
            *(float4*)(sB + r * SB_STRIDE + c4 * 4) = w24[r * 36 + c40 + c4];
        }
        __syncthreads();

        float acc2[4][5];
        #pragma unroll
        for (int i = 0; i < 4; i++)
            #pragma unroll
            for (int j = 0; j < 5; j++) acc2[i][j] = 0.f;

        #pragma unroll 2
        for (int k = 0; k < 64; k++) {
            float a0 = sA[(ty * 4 + 0) * SA_STRIDE + k];
            float a1 = sA[(ty * 4 + 1) * SA_STRIDE + k];
            float a2 = sA[(ty * 4 + 2) * SA_STRIDE + k];
            float a3 = sA[(ty * 4 + 3) * SA_STRIDE + k];
            #pragma unroll
            for (int j = 0; j < 5; j++) {
                if (j < jn) {
                    float b = sB[k * SB_STRIDE + tx + 16 * j];
                    acc2[0][j] += a0 * b;
                    acc2[1][j] += a1 * b;
                    acc2[2][j] += a2 * b;
                    acc2[3][j] += a3 * b;
                }
            }
        }

        #pragma unroll
        for (int j = 0; j < 5; j++) {
            if (j < jn) {
                int e = tx + 16 * (jlo + j);
                float bj = b2[e];
                #pragma unroll
                for (int i = 0; i < 4; i++) {
                    kout[(size_t)(p0 + ty * 4 + i) * EE + e] = acc2[i][j] + bj;
                }
            }
        }
        __syncthreads();   // before next pass overwrites sB
    }
}

// ---------------------------------------------------------------------------
// Involution: out[b,h,w,c] = sum_k x[b, h+ki-1, w+kj-1, c] * ker[b,h,w, k*16 + c%16]
// Block = 1024 threads = 16 pixels (4x4 spatial tile) x 64 float4-chunks.
// Kernel values staged in smem; x via coalesced float4 LDG with halo reuse in L1/L2.
// ---------------------------------------------------------------------------
__global__ void __launch_bounds__(1024, 1)
inv_kernel(const float* __restrict__ x, const float* __restrict__ kern,
           float* __restrict__ out) {
    __shared__ float sk[16 * EE];   // 16 pixels * 144 floats = 9216 B

    const int tid = threadIdx.x;
    int bid = blockIdx.x;
    const int tilesW = WW / 4;      // 32
    const int tilesH = HH / 4;      // 32
    int tw = bid % tilesW; bid /= tilesW;
    int th = bid % tilesH; bid /= tilesH;
    int b  = bid;
    int h0 = th * 4, w0 = tw * 4;

    // stage 16 pixels' kernels (2304 floats)
    for (int idx = tid; idx < 16 * EE; idx += 1024) {
        int pl = idx / EE;
        int e  = idx - pl * EE;
        int hh = h0 + (pl >> 2), ww = w0 + (pl & 3);
        sk[idx] = kern[(size_t)(((b * HH) + hh) * WW + ww) * EE + e];
    }
    __syncthreads();

    const int pl = tid >> 6;        // 0..15 pixel in tile
    const int cc = tid & 63;        // float4 chunk: channels cc*4 .. cc*4+3
    const int hh = h0 + (pl >> 2);
    const int ww = w0 + (pl & 3);
    const int g0 = (cc & 3) * 4;    // (c % 16) for the 4 channels, contiguous

    const float4* x4 = (const float4*)x;
    float4 acc = make_float4(0.f, 0.f, 0.f, 0.f);

    #pragma unroll
    for (int ki = 0; ki < 3; ki++) {
        int hn = hh + ki - 1;
        bool hok = (unsigned)hn < (unsigned)HH;
        #pragma unroll
        for (int kj = 0; kj < 3; kj++) {
            int wn = ww + kj - 1;
            bool ok = hok && ((unsigned)wn < (unsigned)WW);
            float4 xv = ok ? x4[(size_t)((b * HH + hn) * WW + wn) * 64 + cc]
                           : make_float4(0.f, 0.f, 0.f, 0.f);
            float4 kv = *(const float4*)(sk + pl * EE + (ki * 3 + kj) * GG + g0);
            acc.x += xv.x * kv.x;
            acc.y += xv.y * kv.y;
            acc.z += xv.z * kv.z;
            acc.w += xv.w * kv.w;
        }
    }
    ((float4*)out)[(size_t)((b * HH + hh) * WW + ww) * 64 + cc] = acc;
}

// ---------------------------------------------------------------------------
// Launch. Output tuple layout: out (B*H*W*C floats) then kernel (B*H*W*K2*G).
// Launch-only host code: no attributes, no allocation, fully graph-capturable.
// ---------------------------------------------------------------------------
extern "C" void kernel_launch(void* const* d_in, const int* in_sizes, int n_in,
                              void* d_out, int out_size) {
    const float* x     = (const float*)d_in[0];
    const float* w1    = (const float*)d_in[1];
    const float* b1    = (const float*)d_in[2];
    const float* gamma = (const float*)d_in[3];
    const float* beta  = (const float*)d_in[4];
    const float* mean  = (const float*)d_in[5];
    const float* var   = (const float*)d_in[6];
    const float* w2    = (const float*)d_in[7];
    const float* b2    = (const float*)d_in[8];

    float* out  = (float*)d_out;
    float* kout = out + (size_t)NPIX * CC;   // second output tensor

    fold_kernel<<<(CC * CR + 255) / 256, 256>>>(w1, b1, gamma, beta, mean, var);
    kgen_kernel<<<NPIX / 64, 256>>>(x, w2, b2, kout);
    inv_kernel<<<NPIX / 16, 1024>>>(x, kout, out);
}

// round 5
// speedup vs baseline: 1.2751x; 1.2751x over previous
#include <cuda_runtime.h>
#include <cuda_bf16.h>
#include <cstdint>

// Problem constants
#define BATCH 4
#define HH    128
#define WW    128
#define CC    256
#define GG    16
#define CR    64
#define EE    144            // K2*G
#define NPIX  (BATCH*HH*WW)  // 65536

// ---------------------------------------------------------------------------
// Precomputed weights: BN folded scale/bias + bf16 hi/lo splits (transposed)
//   g_w1hi/lo : [n=64][k=256]   (B col-major for mma: n rows, k contiguous)
//   g_w2hi/lo : [n=144][k=64]
// ---------------------------------------------------------------------------
__device__ float g_s[CR];
__device__ float g_b1f[CR];
__device__ __align__(16) __nv_bfloat16 g_w1hi[CR * CC];
__device__ __align__(16) __nv_bfloat16 g_w1lo[CR * CC];
__device__ __align__(16) __nv_bfloat16 g_w2hi[EE * CR];
__device__ __align__(16) __nv_bfloat16 g_w2lo[EE * CR];

__global__ void fold_kernel(const float* __restrict__ w1, const float* __restrict__ b1,
                            const float* __restrict__ gamma, const float* __restrict__ beta,
                            const float* __restrict__ mean, const float* __restrict__ var,
                            const float* __restrict__ w2) {
    int idx = blockIdx.x * blockDim.x + threadIdx.x;
    if (idx < CR) {
        float s = gamma[idx] * rsqrtf(var[idx] + 1e-3f);
        g_s[idx] = s;
        g_b1f[idx] = (b1[idx] - mean[idx]) * s + beta[idx];
    }
    if (idx < CR * CC) {            // w1 transpose + split: [k=256][n=64] -> [n][k]
        int n = idx >> 8, k = idx & 255;
        float v = w1[k * CR + n];
        __nv_bfloat16 h = __float2bfloat16(v);
        g_w1hi[idx] = h;
        g_w1lo[idx] = __float2bfloat16(v - __bfloat162float(h));
    } else {
        int j = idx - CR * CC;
        if (j < EE * CR) {          // w2 transpose + split: [k=64][n=144] -> [n][k]
            int n = j >> 6, k = j & 63;
            float v = w2[k * EE + n];
            __nv_bfloat16 h = __float2bfloat16(v);
            g_w2hi[j] = h;
            g_w2lo[j] = __float2bfloat16(v - __bfloat162float(h));
        }
    }
}

// ---------------------------------------------------------------------------
// mma.sync m16n8k16 bf16 (sm_80+, works on plain sm_100 target)
// A frag (4 b32): R0=(row g,  k 2t..2t+1) R1=(row g+8, k-lo) R2=(g, k-hi) R3=(g+8, k-hi)
// B frag (2 b32): R0=(k 2t..2t+1, n g)    R1=(k+8 pair, n g)
// D frag (4 f32): c0=(g,2t) c1=(g,2t+1) c2=(g+8,2t) c3=(g+8,2t+1)
// ---------------------------------------------------------------------------
#define MMA16816(d, a0, a1, a2, a3, b0, b1) \
    asm volatile("mma.sync.aligned.m16n8k16.row.col.f32.bf16.bf16.f32 " \
        "{%0,%1,%2,%3}, {%4,%5,%6,%7}, {%8,%9}, {%0,%1,%2,%3};" \
        : "+f"((d)[0]), "+f"((d)[1]), "+f"((d)[2]), "+f"((d)[3]) \
        : "r"(a0), "r"(a1), "r"(a2), "r"(a3), "r"(b0), "r"(b1))

__device__ __forceinline__ uint32_t pack_bf16x2(float a, float b) {
    unsigned short ua = __bfloat16_as_ushort(__float2bfloat16(a));
    unsigned short ub = __bfloat16_as_ushort(__float2bfloat16(b));
    return (uint32_t)ua | ((uint32_t)ub << 16);
}

// ---------------------------------------------------------------------------
// Kernel generation on mma.sync (bf16 hi/lo 3-term, fp32 accumulate):
//   GEMM1: D1[128,64]  = x[128,256] @ w1       (K chunks of 32 via smem)
//   epi1 : h = relu(D1*s + b1f)  -> bf16 hi/lo A-frags IN REGISTERS
//   GEMM2: D2[128,144] = h[128,64] @ w2        (two N-halves of 72)
// CTA: 256 threads = 8 warps, 128 pixels; warp w owns rows [16w,16w+16).
// smem: x tile hi/lo [128][40] bf16 (stride-40 conflict-free) = 20 KB
//       w  tile hi/lo (w1 chunks [64][40] / w2 half [72][72])  = 23 KB
// ---------------------------------------------------------------------------
#define XST 40     // x smem stride (bf16)
#define W2ST 72    // w2 smem stride (bf16)

__global__ void __launch_bounds__(256, 2)
kgen_mma(const float* __restrict__ x, const float* __restrict__ b2g,
         float* __restrict__ kout) {
    __shared__ __align__(16) __nv_bfloat16 s_xhi[128 * XST];
    __shared__ __align__(16) __nv_bfloat16 s_xlo[128 * XST];
    __shared__ __align__(16) __nv_bfloat16 s_whi[144 * XST];   // also holds 72*W2ST=5184<5760
    __shared__ __align__(16) __nv_bfloat16 s_wlo[144 * XST];
    __shared__ float s_s[CR];
    __shared__ float s_b1f[CR];
    __shared__ float s_b2[EE];

    const int tid  = threadIdx.x;
    const int lane = tid & 31;
    const int warp = tid >> 5;
    const int g    = lane >> 2;    // group id (row within 8-row half / n within tile)
    const int t    = lane & 3;     // thread-in-group (k-pair / n-pair selector)
    const int p0   = blockIdx.x * 128;
    const int row0 = warp * 16;

    if (tid < CR) { s_s[tid] = g_s[tid]; s_b1f[tid] = g_b1f[tid]; }
    if (tid >= 64 && tid < 64 + EE) s_b2[tid - 64] = b2g[tid - 64];

    float acc1[8][4];
    #pragma unroll
    for (int j = 0; j < 8; j++)
        #pragma unroll
        for (int i = 0; i < 4; i++) acc1[j][i] = 0.f;

    // =============== GEMM1: 8 K-chunks of 32 ===============
    const int px   = tid >> 1;         // 0..127
    const int half = tid & 1;          // 0..1 (16 floats each)
    for (int kc = 0; kc < 8; kc++) {
        // stage x chunk (convert f32 -> bf16 hi/lo)
        {
            const float4* src = ((const float4*)x) + (size_t)(p0 + px) * 64 + kc * 8 + half * 4;
            int kl = half * 16;
            #pragma unroll
            for (int i = 0; i < 4; i++) {
                float4 v = src[i];
                __nv_bfloat16 h0 = __float2bfloat16(v.x), h1 = __float2bfloat16(v.y);
                __nv_bfloat16 h2 = __float2bfloat16(v.z), h3 = __float2bfloat16(v.w);
                uint2 hv, lv;
                hv.x = (uint32_t)__bfloat16_as_ushort(h0) | ((uint32_t)__bfloat16_as_ushort(h1) << 16);
                hv.y = (uint32_t)__bfloat16_as_ushort(h2) | ((uint32_t)__bfloat16_as_ushort(h3) << 16);
                lv.x = pack_bf16x2(v.x - __bfloat162float(h0), v.y - __bfloat162float(h1));
                lv.y = pack_bf16x2(v.z - __bfloat162float(h2), v.w - __bfloat162float(h3));
                *(uint2*)(s_xhi + px * XST + kl + i * 4) = hv;
                *(uint2*)(s_xlo + px * XST + kl + i * 4) = lv;
            }
        }
        // stage w1 chunk: [64 n][32 k], 512 uint2 per plane
        #pragma unroll
        for (int it = 0; it < 2; it++) {
            int idx = tid + it * 256;
            int n = idx >> 3, q = idx & 7;
            *(uint2*)(s_whi + n * XST + q * 4) = *(const uint2*)(g_w1hi + n * CC + kc * 32 + q * 4);
            *(uint2*)(s_wlo + n * XST + q * 4) = *(const uint2*)(g_w1lo + n * CC + kc * 32 + q * 4);
        }
        __syncthreads();

        #pragma unroll
        for (int ks = 0; ks < 2; ks++) {
            const int kb = ks * 16 + 2 * t;
            uint32_t ahi[4], alo[4];
            ahi[0] = *(const uint32_t*)(s_xhi + (row0 + g)     * XST + kb);
            ahi[1] = *(const uint32_t*)(s_xhi + (row0 + g + 8) * XST + kb);
            ahi[2] = *(const uint32_t*)(s_xhi + (row0 + g)     * XST + kb + 8);
            ahi[3] = *(const uint32_t*)(s_xhi + (row0 + g + 8) * XST + kb + 8);
            alo[0] = *(const uint32_t*)(s_xlo + (row0 + g)     * XST + kb);
            alo[1] = *(const uint32_t*)(s_xlo + (row0 + g + 8) * XST + kb);
            alo[2] = *(const uint32_t*)(s_xlo + (row0 + g)     * XST + kb + 8);
            alo[3] = *(const uint32_t*)(s_xlo + (row0 + g + 8) * XST + kb + 8);
            #pragma unroll
            for (int nt = 0; nt < 8; nt++) {
                uint32_t bh0 = *(const uint32_t*)(s_whi + (nt * 8 + g) * XST + kb);
                uint32_t bh1 = *(const uint32_t*)(s_whi + (nt * 8 + g) * XST + kb + 8);
                uint32_t bl0 = *(const uint32_t*)(s_wlo + (nt * 8 + g) * XST + kb);
                uint32_t bl1 = *(const uint32_t*)(s_wlo + (nt * 8 + g) * XST + kb + 8);
                MMA16816(acc1[nt], ahi[0], ahi[1], ahi[2], ahi[3], bh0, bh1);
                MMA16816(acc1[nt], ahi[0], ahi[1], ahi[2], ahi[3], bl0, bl1);
                MMA16816(acc1[nt], alo[0], alo[1], alo[2], alo[3], bh0, bh1);
            }
        }
        __syncthreads();
    }

    // =============== epilogue 1: scale+bias+relu -> A2 frags in registers ===============
    // D1 tile j gives h[g / g+8][n=8j+2t(,+1)]. For GEMM2 (K=64 = old n dim),
    // A frag for k-step ks: k-lo pair from tile 2ks, k-hi pair from tile 2ks+1.
    uint32_t a2hi[4][4], a2lo[4][4];
    #pragma unroll
    for (int j = 0; j < 8; j++) {
        int n0 = 8 * j + 2 * t;
        float sc0 = s_s[n0], sc1 = s_s[n0 + 1];
        float bb0 = s_b1f[n0], bb1 = s_b1f[n0 + 1];
        float v0 = fmaxf(acc1[j][0] * sc0 + bb0, 0.f);
        float v1 = fmaxf(acc1[j][1] * sc1 + bb1, 0.f);
        float v2 = fmaxf(acc1[j][2] * sc0 + bb0, 0.f);
        float v3 = fmaxf(acc1[j][3] * sc1 + bb1, 0.f);
        int ks = j >> 1, hh = (j & 1) * 2;
        __nv_bfloat16 h0 = __float2bfloat16(v0), h1 = __float2bfloat16(v1);
        __nv_bfloat16 h2 = __float2bfloat16(v2), h3 = __float2bfloat16(v3);
        a2hi[ks][hh + 0] = (uint32_t)__bfloat16_as_ushort(h0) | ((uint32_t)__bfloat16_as_ushort(h1) << 16);
        a2hi[ks][hh + 1] = (uint32_t)__bfloat16_as_ushort(h2) | ((uint32_t)__bfloat16_as_ushort(h3) << 16);
        a2lo[ks][hh + 0] = pack_bf16x2(v0 - __bfloat162float(h0), v1 - __bfloat162float(h1));
        a2lo[ks][hh + 1] = pack_bf16x2(v2 - __bfloat162float(h2), v3 - __bfloat162float(h3));
    }
    // NOTE: frag reg order is {R0=(g,klo),R1=(g+8,klo),R2=(g,khi),R3=(g+8,khi)}:
    // here a2*[ks] = {tile2ks:(g),(g+8), tile2ks+1:(g),(g+8)} == {R0,R1,R2,R3}. Correct.

    // =============== GEMM2: two N-halves of 72 (9 n-tiles each) ===============
    #pragma unroll 1
    for (int nh = 0; nh < 2; nh++) {
        // stage w2 half: rows [72*nh, +72), full K=64, stride W2ST. 1152 uint2/plane.
        #pragma unroll
        for (int it = 0; it < 5; it++) {
            int idx = tid + it * 256;
            if (idx < 1152) {
                int n = idx >> 4, q = idx & 15;
                *(uint2*)(s_whi + n * W2ST + q * 4) =
                    *(const uint2*)(g_w2hi + (nh * 72 + n) * CR + q * 4);
                *(uint2*)(s_wlo + n * W2ST + q * 4) =
                    *(const uint2*)(g_w2lo + (nh * 72 + n) * CR + q * 4);
            }
        }
        __syncthreads();

        float acc2[9][4];
        #pragma unroll
        for (int j = 0; j < 9; j++)
            #pragma unroll
            for (int i = 0; i < 4; i++) acc2[j][i] = 0.f;

        #pragma unroll
        for (int ks = 0; ks < 4; ks++) {
            const int kb = ks * 16 + 2 * t;
            #pragma unroll
            for (int nt = 0; nt < 9; nt++) {
                uint32_t bh0 = *(const uint32_t*)(s_whi + (nt * 8 + g) * W2ST + kb);
                uint32_t bh1 = *(const uint32_t*)(s_whi + (nt * 8 + g) * W2ST + kb + 8);
                uint32_t bl0 = *(const uint32_t*)(s_wlo + (nt * 8 + g) * W2ST + kb);
                uint32_t bl1 = *(const uint32_t*)(s_wlo + (nt * 8 + g) * W2ST + kb + 8);
                MMA16816(acc2[nt], a2hi[ks][0], a2hi[ks][1], a2hi[ks][2], a2hi[ks][3], bh0, bh1);
                MMA16816(acc2[nt], a2hi[ks][0], a2hi[ks][1], a2hi[ks][2], a2hi[ks][3], bl0, bl1);
                MMA16816(acc2[nt], a2lo[ks][0], a2lo[ks][1], a2lo[ks][2], a2lo[ks][3], bh0, bh1);
            }
        }

        // epilogue: + b2, write kernel output for this half
        const int r0 = p0 + row0 + g;
        #pragma unroll
        for (int nt = 0; nt < 9; nt++) {
            int n0 = nh * 72 + nt * 8 + 2 * t;
            float2 v01 = make_float2(acc2[nt][0] + s_b2[n0], acc2[nt][1] + s_b2[n0 + 1]);
            float2 v23 = make_float2(acc2[nt][2] + s_b2[n0], acc2[nt][3] + s_b2[n0 + 1]);
            *(float2*)(kout + (size_t)r0 * EE + n0)       = v01;
            *(float2*)(kout + (size_t)(r0 + 8) * EE + n0) = v23;
        }
        __syncthreads();
    }
}

// ---------------------------------------------------------------------------
// Involution: out[b,h,w,c] = sum_k x[b, h+ki-1, w+kj-1, c] * ker[b,h,w, k*16 + c%16]
// Block = 1024 threads = 16 pixels (4x4 spatial tile) x 64 float4-chunks.
// ---------------------------------------------------------------------------
__global__ void __launch_bounds__(1024, 1)
inv_kernel(const float* __restrict__ x, const float* __restrict__ kern,
           float* __restrict__ out) {
    __shared__ float sk[16 * EE];

    const int tid = threadIdx.x;
    int bid = blockIdx.x;
    int tw = bid & 31; bid >>= 5;
    int th = bid & 31; bid >>= 5;
    int b  = bid;
    int h0 = th * 4, w0 = tw * 4;

    for (int idx = tid; idx < 16 * EE; idx += 1024) {
        int pl = idx / EE;
        int e  = idx - pl * EE;
        int hh = h0 + (pl >> 2), ww = w0 + (pl & 3);
        sk[idx] = kern[(size_t)(((b * HH) + hh) * WW + ww) * EE + e];
    }
    __syncthreads();

    const int pl = tid >> 6;
    const int cc = tid & 63;
    const int hh = h0 + (pl >> 2);
    const int ww = w0 + (pl & 3);
    const int g0 = (cc & 3) * 4;

    const float4* x4 = (const float4*)x;
    float4 acc = make_float4(0.f, 0.f, 0.f, 0.f);

    #pragma unroll
    for (int ki = 0; ki < 3; ki++) {
        int hn = hh + ki - 1;
        bool hok = (unsigned)hn < (unsigned)HH;
        #pragma unroll
        for (int kj = 0; kj < 3; kj++) {
            int wn = ww + kj - 1;
            bool ok = hok && ((unsigned)wn < (unsigned)WW);
            float4 xv = ok ? x4[(size_t)((b * HH + hn) * WW + wn) * 64 + cc]
                           : make_float4(0.f, 0.f, 0.f, 0.f);
            float4 kv = *(const float4*)(sk + pl * EE + (ki * 3 + kj) * GG + g0);
            acc.x += xv.x * kv.x;
            acc.y += xv.y * kv.y;
            acc.z += xv.z * kv.z;
            acc.w += xv.w * kv.w;
        }
    }
    ((float4*)out)[(size_t)((b * HH + hh) * WW + ww) * 64 + cc] = acc;
}

// ---------------------------------------------------------------------------
extern "C" void kernel_launch(void* const* d_in, const int* in_sizes, int n_in,
                              void* d_out, int out_size) {
    const float* x     = (const float*)d_in[0];
    const float* w1    = (const float*)d_in[1];
    const float* b1    = (const float*)d_in[2];
    const float* gamma = (const float*)d_in[3];
    const float* beta  = (const float*)d_in[4];
    const float* mean  = (const float*)d_in[5];
    const float* var   = (const float*)d_in[6];
    const float* w2    = (const float*)d_in[7];
    const float* b2    = (const float*)d_in[8];

    float* out  = (float*)d_out;
    float* kout = out + (size_t)NPIX * CC;

    fold_kernel<<<(CR * CC + EE * CR + 255) / 256, 256>>>(w1, b1, gamma, beta, mean, var, w2);
    kgen_mma<<<NPIX / 128, 256>>>(x, b2, kout);
    inv_kernel<<<NPIX / 16, 1024>>>(x, kout, out);
}

// round 8
// speedup vs baseline: 1.3056x; 1.0239x over previous
#include <cuda_runtime.h>
#include <cuda_bf16.h>
#include <cstdint>

// Problem constants
#define BATCH 4
#define HH    128
#define WW    128
#define CC    256
#define GG    16
#define CR    64
#define EE    144            // K2*G
#define NPIX  (BATCH*HH*WW)  // 65536

// ---------------------------------------------------------------------------
// Precomputed weights: BN folded scale/bias + bf16 hi/lo splits (transposed)
//   g_w1hi/lo : [n=64][k=256]   (B col-major for mma: n rows, k contiguous)
//   g_w2hi/lo : [n=144][k=64]
// ---------------------------------------------------------------------------
__device__ float g_s[CR];
__device__ float g_b1f[CR];
__device__ __align__(16) __nv_bfloat16 g_w1hi[CR * CC];
__device__ __align__(16) __nv_bfloat16 g_w1lo[CR * CC];
__device__ __align__(16) __nv_bfloat16 g_w2hi[EE * CR];
__device__ __align__(16) __nv_bfloat16 g_w2lo[EE * CR];

__global__ void fold_kernel(const float* __restrict__ w1, const float* __restrict__ b1,
                            const float* __restrict__ gamma, const float* __restrict__ beta,
                            const float* __restrict__ mean, const float* __restrict__ var,
                            const float* __restrict__ w2) {
    int idx = blockIdx.x * blockDim.x + threadIdx.x;
    if (idx < CR) {
        float s = gamma[idx] * rsqrtf(var[idx] + 1e-3f);
        g_s[idx] = s;
        g_b1f[idx] = (b1[idx] - mean[idx]) * s + beta[idx];
    }
    if (idx < CR * CC) {            // w1 transpose + split: [k=256][n=64] -> [n][k]
        int n = idx >> 8, k = idx & 255;
        float v = w1[k * CR + n];
        __nv_bfloat16 h = __float2bfloat16(v);
        g_w1hi[idx] = h;
        g_w1lo[idx] = __float2bfloat16(v - __bfloat162float(h));
    } else {
        int j = idx - CR * CC;
        if (j < EE * CR) {          // w2 transpose + split: [k=64][n=144] -> [n][k]
            int n = j >> 6, k = j & 63;
            float v = w2[k * EE + n];
            __nv_bfloat16 h = __float2bfloat16(v);
            g_w2hi[j] = h;
            g_w2lo[j] = __float2bfloat16(v - __bfloat162float(h));
        }
    }
}

// ---------------------------------------------------------------------------
// mma.sync m16n8k16 bf16 (sm_80+, works on plain sm_100 target)
// ---------------------------------------------------------------------------
#define MMA16816(d, a0, a1, a2, a3, b0, b1) \
    asm volatile("mma.sync.aligned.m16n8k16.row.col.f32.bf16.bf16.f32 " \
        "{%0,%1,%2,%3}, {%4,%5,%6,%7}, {%8,%9}, {%0,%1,%2,%3};" \
        : "+f"((d)[0]), "+f"((d)[1]), "+f"((d)[2]), "+f"((d)[3]) \
        : "r"(a0), "r"(a1), "r"(a2), "r"(a3), "r"(b0), "r"(b1))

__device__ __forceinline__ uint32_t pack_bf16x2(float a, float b) {
    unsigned short ua = __bfloat16_as_ushort(__float2bfloat16(a));
    unsigned short ub = __bfloat16_as_ushort(__float2bfloat16(b));
    return (uint32_t)ua | ((uint32_t)ub << 16);
}

// ---------------------------------------------------------------------------
// Kernel generation on mma.sync (bf16 hi/lo 3-term, fp32 accumulate).
// GEMM1 mainloop: x (DRAM-critical operand) is register double-buffered —
// the next chunk's 4x float4 loads are issued right after the staging sync,
// overlapping their ~600cyc latency with the 48 MMAs of the current chunk.
// w1 (64KB, L2-resident after wave 1) is staged directly as in R5.
// ---------------------------------------------------------------------------
#define XST 40     // x smem stride (bf16)
#define W2ST 72    // w2 smem stride (bf16)

__global__ void __launch_bounds__(256, 2)
kgen_mma(const float* __restrict__ x, const float* __restrict__ b2g,
         float* __restrict__ kout) {
    __shared__ __align__(16) __nv_bfloat16 s_xhi[128 * XST];
    __shared__ __align__(16) __nv_bfloat16 s_xlo[128 * XST];
    __shared__ __align__(16) __nv_bfloat16 s_whi[144 * XST];   // also holds 72*W2ST
    __shared__ __align__(16) __nv_bfloat16 s_wlo[144 * XST];
    __shared__ float s_s[CR];
    __shared__ float s_b1f[CR];
    __shared__ float s_b2[EE];

    const int tid  = threadIdx.x;
    const int lane = tid & 31;
    const int warp = tid >> 5;
    const int g    = lane >> 2;
    const int t    = lane & 3;
    const int p0   = blockIdx.x * 128;
    const int row0 = warp * 16;

    if (tid < CR) { s_s[tid] = g_s[tid]; s_b1f[tid] = g_b1f[tid]; }
    if (tid >= 64 && tid < 64 + EE) s_b2[tid - 64] = b2g[tid - 64];

    float acc1[8][4];
    #pragma unroll
    for (int j = 0; j < 8; j++)
        #pragma unroll
        for (int i = 0; i < 4; i++) acc1[j][i] = 0.f;

    // =============== GEMM1: 8 K-chunks of 32, x register double-buffered ===============
    const int px   = tid >> 1;         // 0..127
    const int half = tid & 1;
    const float4* xbase = ((const float4*)x) + (size_t)(p0 + px) * 64 + half * 4;

    float4 xr0, xr1, xr2, xr3;
    {
        const float4* s0 = xbase;
        xr0 = s0[0]; xr1 = s0[1]; xr2 = s0[2]; xr3 = s0[3];
    }

    for (int kc = 0; kc < 8; kc++) {
        // stage prefetched x regs -> smem (convert f32 -> bf16 hi/lo)
        {
            const int kl = half * 16;
            float4 vv[4] = {xr0, xr1, xr2, xr3};
            #pragma unroll
            for (int i = 0; i < 4; i++) {
                float4 v = vv[i];
                __nv_bfloat16 h0 = __float2bfloat16(v.x), h1 = __float2bfloat16(v.y);
                __nv_bfloat16 h2 = __float2bfloat16(v.z), h3 = __float2bfloat16(v.w);
                uint2 hv, lv;
                hv.x = (uint32_t)__bfloat16_as_ushort(h0) | ((uint32_t)__bfloat16_as_ushort(h1) << 16);
                hv.y = (uint32_t)__bfloat16_as_ushort(h2) | ((uint32_t)__bfloat16_as_ushort(h3) << 16);
                lv.x = pack_bf16x2(v.x - __bfloat162float(h0), v.y - __bfloat162float(h1));
                lv.y = pack_bf16x2(v.z - __bfloat162float(h2), v.w - __bfloat162float(h3));
                *(uint2*)(s_xhi + px * XST + kl + i * 4) = hv;
                *(uint2*)(s_xlo + px * XST + kl + i * 4) = lv;
            }
        }
        // stage w1 chunk: [64 n][32 k], 512 uint2 per plane (L2-resident; as in R5)
        #pragma unroll
        for (int it = 0; it < 2; it++) {
            int idx = tid + it * 256;
            int n = idx >> 3, q = idx & 7;
            *(uint2*)(s_whi + n * XST + q * 4) = *(const uint2*)(g_w1hi + n * CC + kc * 32 + q * 4);
            *(uint2*)(s_wlo + n * XST + q * 4) = *(const uint2*)(g_w1lo + n * CC + kc * 32 + q * 4);
        }
        __syncthreads();

        // issue next chunk's x loads now; DRAM latency overlaps the MMAs below
        if (kc < 7) {
            const float4* sn = xbase + (kc + 1) * 8;
            xr0 = sn[0]; xr1 = sn[1]; xr2 = sn[2]; xr3 = sn[3];
        }

        #pragma unroll
        for (int ks = 0; ks < 2; ks++) {
            const int kb = ks * 16 + 2 * t;
            uint32_t ahi[4], alo[4];
            ahi[0] = *(const uint32_t*)(s_xhi + (row0 + g)     * XST + kb);
            ahi[1] = *(const uint32_t*)(s_xhi + (row0 + g + 8) * XST + kb);
            ahi[2] = *(const uint32_t*)(s_xhi + (row0 + g)     * XST + kb + 8);
            ahi[3] = *(const uint32_t*)(s_xhi + (row0 + g + 8) * XST + kb + 8);
            alo[0] = *(const uint32_t*)(s_xlo + (row0 + g)     * XST + kb);
            alo[1] = *(const uint32_t*)(s_xlo + (row0 + g + 8) * XST + kb);
            alo[2] = *(const uint32_t*)(s_xlo + (row0 + g)     * XST + kb + 8);
            alo[3] = *(const uint32_t*)(s_xlo + (row0 + g + 8) * XST + kb + 8);
            #pragma unroll
            for (int nt = 0; nt < 8; nt++) {
                uint32_t bh0 = *(const uint32_t*)(s_whi + (nt * 8 + g) * XST + kb);
                uint32_t bh1 = *(const uint32_t*)(s_whi + (nt * 8 + g) * XST + kb + 8);
                uint32_t bl0 = *(const uint32_t*)(s_wlo + (nt * 8 + g) * XST + kb);
                uint32_t bl1 = *(const uint32_t*)(s_wlo + (nt * 8 + g) * XST + kb + 8);
                MMA16816(acc1[nt], ahi[0], ahi[1], ahi[2], ahi[3], bh0, bh1);
                MMA16816(acc1[nt], ahi[0], ahi[1], ahi[2], ahi[3], bl0, bl1);
                MMA16816(acc1[nt], alo[0], alo[1], alo[2], alo[3], bh0, bh1);
            }
        }
        __syncthreads();
    }

    // =============== epilogue 1: scale+bias+relu -> A2 frags in registers ===============
    uint32_t a2hi[4][4], a2lo[4][4];
    #pragma unroll
    for (int j = 0; j < 8; j++) {
        int n0 = 8 * j + 2 * t;
        float sc0 = s_s[n0], sc1 = s_s[n0 + 1];
        float bb0 = s_b1f[n0], bb1 = s_b1f[n0 + 1];
        float v0 = fmaxf(acc1[j][0] * sc0 + bb0, 0.f);
        float v1 = fmaxf(acc1[j][1] * sc1 + bb1, 0.f);
        float v2 = fmaxf(acc1[j][2] * sc0 + bb0, 0.f);
        float v3 = fmaxf(acc1[j][3] * sc1 + bb1, 0.f);
        int ks = j >> 1, hh = (j & 1) * 2;
        __nv_bfloat16 h0 = __float2bfloat16(v0), h1 = __float2bfloat16(v1);
        __nv_bfloat16 h2 = __float2bfloat16(v2), h3 = __float2bfloat16(v3);
        a2hi[ks][hh + 0] = (uint32_t)__bfloat16_as_ushort(h0) | ((uint32_t)__bfloat16_as_ushort(h1) << 16);
        a2hi[ks][hh + 1] = (uint32_t)__bfloat16_as_ushort(h2) | ((uint32_t)__bfloat16_as_ushort(h3) << 16);
        a2lo[ks][hh + 0] = pack_bf16x2(v0 - __bfloat162float(h0), v1 - __bfloat162float(h1));
        a2lo[ks][hh + 1] = pack_bf16x2(v2 - __bfloat162float(h2), v3 - __bfloat162float(h3));
    }

    // =============== GEMM2: two N-halves of 72 (9 n-tiles each) ===============
    #pragma unroll 1
    for (int nh = 0; nh < 2; nh++) {
        #pragma unroll
        for (int it = 0; it < 5; it++) {
            int idx = tid + it * 256;
            if (idx < 1152) {
                int n = idx >> 4, q = idx & 15;
                *(uint2*)(s_whi + n * W2ST + q * 4) =
                    *(const uint2*)(g_w2hi + (nh * 72 + n) * CR + q * 4);
                *(uint2*)(s_wlo + n * W2ST + q * 4) =
                    *(const uint2*)(g_w2lo + (nh * 72 + n) * CR + q * 4);
            }
        }
        __syncthreads();

        float acc2[9][4];
        #pragma unroll
        for (int j = 0; j < 9; j++)
            #pragma unroll
            for (int i = 0; i < 4; i++) acc2[j][i] = 0.f;

        #pragma unroll
        for (int ks = 0; ks < 4; ks++) {
            const int kb = ks * 16 + 2 * t;
            #pragma unroll
            for (int nt = 0; nt < 9; nt++) {
                uint32_t bh0 = *(const uint32_t*)(s_whi + (nt * 8 + g) * W2ST + kb);
                uint32_t bh1 = *(const uint32_t*)(s_whi + (nt * 8 + g) * W2ST + kb + 8);
                uint32_t bl0 = *(const uint32_t*)(s_wlo + (nt * 8 + g) * W2ST + kb);
                uint32_t bl1 = *(const uint32_t*)(s_wlo + (nt * 8 + g) * W2ST + kb + 8);
                MMA16816(acc2[nt], a2hi[ks][0], a2hi[ks][1], a2hi[ks][2], a2hi[ks][3], bh0, bh1);
                MMA16816(acc2[nt], a2hi[ks][0], a2hi[ks][1], a2hi[ks][2], a2hi[ks][3], bl0, bl1);
                MMA16816(acc2[nt], a2lo[ks][0], a2lo[ks][1], a2lo[ks][2], a2lo[ks][3], bh0, bh1);
            }
        }

        const int r0 = p0 + row0 + g;
        #pragma unroll
        for (int nt = 0; nt < 9; nt++) {
            int n0 = nh * 72 + nt * 8 + 2 * t;
            float2 v01 = make_float2(acc2[nt][0] + s_b2[n0], acc2[nt][1] + s_b2[n0 + 1]);
            float2 v23 = make_float2(acc2[nt][2] + s_b2[n0], acc2[nt][3] + s_b2[n0 + 1]);
            *(float2*)(kout + (size_t)r0 * EE + n0)       = v01;
            *(float2*)(kout + (size_t)(r0 + 8) * EE + n0) = v23;
        }
        __syncthreads();
    }
}

// ---------------------------------------------------------------------------
// Involution: out[b,h,w,c] = sum_k x[b, h+ki-1, w+kj-1, c] * ker[b,h,w, k*16 + c%16]
// (unchanged for clean attribution)
// ---------------------------------------------------------------------------
__global__ void __launch_bounds__(1024, 1)
inv_kernel(const float* __restrict__ x, const float* __restrict__ kern,
           float* __restrict__ out) {
    __shared__ float sk[16 * EE];

    const int tid = threadIdx.x;
    int bid = blockIdx.x;
    int tw = bid & 31; bid >>= 5;
    int th = bid & 31; bid >>= 5;
    int b  = bid;
    int h0 = th * 4, w0 = tw * 4;

    for (int idx = tid; idx < 16 * EE; idx += 1024) {
        int pl = idx / EE;
        int e  = idx - pl * EE;
        int hh = h0 + (pl >> 2), ww = w0 + (pl & 3);
        sk[idx] = kern[(size_t)(((b * HH) + hh) * WW + ww) * EE + e];
    }
    __syncthreads();

    const int pl = tid >> 6;
    const int cc = tid & 63;
    const int hh = h0 + (pl >> 2);
    const int ww = w0 + (pl & 3);
    const int g0 = (cc & 3) * 4;

    const float4* x4 = (const float4*)x;
    float4 acc = make_float4(0.f, 0.f, 0.f, 0.f);

    #pragma unroll
    for (int ki = 0; ki < 3; ki++) {
        int hn = hh + ki - 1;
        bool hok = (unsigned)hn < (unsigned)HH;
        #pragma unroll
        for (int kj = 0; kj < 3; kj++) {
            int wn = ww + kj - 1;
            bool ok = hok && ((unsigned)wn < (unsigned)WW);
            float4 xv = ok ? x4[(size_t)((b * HH + hn) * WW + wn) * 64 + cc]
                           : make_float4(0.f, 0.f, 0.f, 0.f);
            float4 kv = *(const float4*)(sk + pl * EE + (ki * 3 + kj) * GG + g0);
            acc.x += xv.x * kv.x;
            acc.y += xv.y * kv.y;
            acc.z += xv.z * kv.z;
            acc.w += xv.w * kv.w;
        }
    }
    ((float4*)out)[(size_t)((b * HH + hh) * WW + ww) * 64 + cc] = acc;
}

// ---------------------------------------------------------------------------
extern "C" void kernel_launch(void* const* d_in, const int* in_sizes, int n_in,
                              void* d_out, int out_size) {
    const float* x     = (const float*)d_in[0];
    const float* w1    = (const float*)d_in[1];
    const float* b1    = (const float*)d_in[2];
    const float* gamma = (const float*)d_in[3];
    const float* beta  = (const float*)d_in[4];
    const float* mean  = (const float*)d_in[5];
    const float* var   = (const float*)d_in[6];
    const float* w2    = (const float*)d_in[7];
    const float* b2    = (const float*)d_in[8];

    float* out  = (float*)d_out;
    float* kout = out + (size_t)NPIX * CC;

    fold_kernel<<<(CR * CC + EE * CR + 255) / 256, 256>>>(w1, b1, gamma, beta, mean, var, w2);
    kgen_mma<<<NPIX / 128, 256>>>(x, b2, kout);
    inv_kernel<<<NPIX / 16, 1024>>>(x, kout, out);
}